// round 9
// baseline (speedup 1.0000x reference)
#include <cuda_runtime.h>
#include <cuda_bf16.h>
#include <mma.h>
#include <cstdint>

#define NB 16
#define SEQL 20
#define PP 1024
#define VD 256
#define HND 512
#define EMBD 300
#define M_TOT (NB*PP)      // 16384
#define KCONV 2304

typedef __nv_bfloat16 bf16;
using namespace nvcuda;

// ---------------- device scratch ----------------
__device__ float g_feat [M_TOT*VD];
__device__ float g_tpre [M_TOT*VD];
__device__ float g_t    [M_TOT*VD];
__device__ float g_khvv [M_TOT*2*VD];
__device__ float g_fea  [M_TOT*VD];
__device__ float g_tmp  [M_TOT*VD];
__device__ float g_tmp2 [M_TOT*VD];
__device__ float g_qh   [SEQL*NB*VD];
__device__ float g_thn  [NB*9*VD];
__device__ float g_sp   [PP*VD];
__device__ float g_bkv  [2*VD];

// bf16 hi/lo activation buffers
__device__ bf16 g_feat_h[M_TOT*VD], g_feat_l[M_TOT*VD];
__device__ bf16 g_t_h[M_TOT*VD],    g_t_l[M_TOT*VD];
__device__ bf16 g_o_h[M_TOT*VD],    g_o_l[M_TOT*VD];
__device__ bf16 g_fea_h[M_TOT*VD],  g_fea_l[M_TOT*VD];
__device__ bf16 g_l1_h[M_TOT*VD],   g_l1_l[M_TOT*VD];

// bf16 hi/lo weights, [n][k] layout
__device__ bf16 g_wc_h[VD*KCONV], g_wc_l[VD*KCONV];
__device__ bf16 g_wkv_h[2*VD*VD], g_wkv_l[2*VD*VD];
__device__ bf16 g_wo_h[VD*VD],    g_wo_l[VD*VD];
__device__ bf16 g_w1_h[VD*VD],    g_w1_l[VD*VD];
__device__ bf16 g_w2_h[VD*VD],    g_w2_l[VD*VD];

// ---------------- helpers (base-target only) ----------------
__device__ __forceinline__ uint32_t smem_u32(const void* p) {
    uint32_t a;
    asm("{ .reg .u64 t; cvta.to.shared.u64 t, %1; cvt.u32.u64 %0, t; }" : "=r"(a) : "l"(p));
    return a;
}
#define CP_COMMIT()      asm volatile("cp.async.commit_group;" ::: "memory")
#define CP_WAIT1()       asm volatile("cp.async.wait_group 1;" ::: "memory")
#define CP_WAIT0()       asm volatile("cp.async.wait_group 0;" ::: "memory")
#define CPA16(d, s)      asm volatile("cp.async.ca.shared.global [%0], [%1], 16;" :: "r"(d), "l"(s) : "memory")
#define CPA16Z(d, s, sz) asm volatile("cp.async.ca.shared.global [%0], [%1], 16, %2;" :: "r"(d), "l"(s), "r"(sz) : "memory")

__device__ __forceinline__ void split2(float v, bf16* h, bf16* l, size_t i) {
    bf16 hh = __float2bfloat16(v);
    h[i] = hh;
    l[i] = __float2bfloat16(v - __bfloat162float(hh));
}

// ---------------- smem layout for gemm_wmma ----------------
// K-chunk 64, skewed rows of 72 bf16 (144 B)
// per stage: A 128x72x2B = 18432  |  B 256x72x2B = 36864  -> 55296 B
// 2 stages = 110592 B; epilogue staging 16 warps x 256 fp32 = 16384 B
#define LDS 72
#define A_BYTES (128*LDS*2)
#define B_BYTES (256*LDS*2)
#define ST_STRIDE (A_BYTES + B_BYTES)
#define B_OFF A_BYTES
#define EPI_OFF (2*ST_STRIDE)
#define SM_TOTAL (2*ST_STRIDE + 16384)

// ---------------- wmma GEMM: C[128 x 256] per CTA, 512 threads ----------------
// K' = 3K via bf16 hi/lo split: seg0 Ah*Bh, seg1 Ah*Bl, seg2 Al*Bh.
// MODE 0: out = D + bias (fp32 and/or hi/lo)
// MODE 1: out = relu(D + bias) -> hi/lo only
// MODE 2 (conv): out = relu(D + sp + thn) -> fp32; A gathered with 3x3 halo
template<int MODE> __global__ void __launch_bounds__(512)
gemm_wmma(const bf16* __restrict__ Ah, const bf16* __restrict__ Al,
          const bf16* __restrict__ Bh, const bf16* __restrict__ Bl,
          const float* __restrict__ bias,
          float* __restrict__ outf, bf16* __restrict__ outh, bf16* __restrict__ outl,
          int K, int ldc, int C, int cps)
{
    extern __shared__ char smem[];
    uint32_t sb = smem_u32(smem);
    int tid = threadIdx.x, wid = tid >> 5, lane = tid & 31;
    int wr = wid >> 2, wc = wid & 3;          // 4x4 warp grid: 32-row x 64-col tiles
    int m0 = blockIdx.y * 128, n0 = blockIdx.x * 256;

    auto loadA = [&](int c, int st) {
        int seg = c / cps;
        int kk = (c - seg * cps) * 64;
        const bf16* src = (seg == 2) ? Al : Ah;
        uint32_t ab = sb + st * ST_STRIDE;
        if (MODE == 2) {
            int tap = kk >> 8, ci0 = kk & 255;
            int dy = tap / 3 - 1, dx = tap % 3 - 1;
            int nimg = m0 >> 10;
#pragma unroll
            for (int r = 0; r < 2; r++) {
                int e = tid + r * 512;         // 1024 quads: 128 rows x 8
                int row = e >> 3, q = e & 7;
                int pix = (m0 + row) & 1023;
                int yy = (pix >> 5) + dy, xx = (pix & 31) + dx;
                bool ok = ((unsigned)yy < 32u) && ((unsigned)xx < 32u);
                const bf16* s = ok ? (src + (((size_t)((nimg << 10) + (yy << 5) + xx)) << 8) + ci0 + q * 8) : src;
                CPA16Z(ab + (row * LDS + q * 8) * 2, s, ok ? 16u : 0u);
            }
        } else {
#pragma unroll
            for (int r = 0; r < 2; r++) {
                int e = tid + r * 512;
                int row = e >> 3, q = e & 7;
                const bf16* s = src + (size_t)(m0 + row) * K + kk + q * 8;
                CPA16(ab + (row * LDS + q * 8) * 2, s);
            }
        }
    };
    auto loadB = [&](int c, int st) {
        int seg = c / cps;
        int kk = (c - seg * cps) * 64;
        const bf16* src = (seg == 1) ? Bl : Bh;
        uint32_t bb = sb + st * ST_STRIDE + B_OFF;
#pragma unroll
        for (int r = 0; r < 4; r++) {
            int e = tid + r * 512;             // 2048 quads: 256 rows x 8
            int row = e >> 3, q = e & 7;
            const bf16* s = src + (size_t)(n0 + row) * K + kk + q * 8;
            CPA16(bb + (row * LDS + q * 8) * 2, s);
        }
    };

    wmma::fragment<wmma::accumulator, 16, 16, 16, float> fc[2][4];
#pragma unroll
    for (int mi = 0; mi < 2; mi++)
#pragma unroll
        for (int ni = 0; ni < 4; ni++) wmma::fill_fragment(fc[mi][ni], 0.f);

    loadA(0, 0); loadB(0, 0); CP_COMMIT();
    if (C > 1) { loadA(1, 1); loadB(1, 1); }
    CP_COMMIT();

    for (int c = 0; c < C; c++) {
        int st = c & 1;
        CP_WAIT1();
        __syncthreads();
        const bf16* As = (const bf16*)(smem + st * ST_STRIDE);
        const bf16* Bs = (const bf16*)(smem + st * ST_STRIDE + B_OFF);
#pragma unroll
        for (int ks = 0; ks < 64; ks += 16) {
            wmma::fragment<wmma::matrix_a, 16, 16, 16, bf16, wmma::row_major> fa[2];
            wmma::fragment<wmma::matrix_b, 16, 16, 16, bf16, wmma::col_major> fb[4];
#pragma unroll
            for (int mi = 0; mi < 2; mi++)
                wmma::load_matrix_sync(fa[mi], As + (wr * 32 + mi * 16) * LDS + ks, LDS);
#pragma unroll
            for (int ni = 0; ni < 4; ni++)
                wmma::load_matrix_sync(fb[ni], Bs + (wc * 64 + ni * 16) * LDS + ks, LDS);
#pragma unroll
            for (int mi = 0; mi < 2; mi++)
#pragma unroll
                for (int ni = 0; ni < 4; ni++)
                    wmma::mma_sync(fc[mi][ni], fa[mi], fb[ni], fc[mi][ni]);
        }
        __syncthreads();
        if (c + 2 < C) { loadA(c + 2, st); loadB(c + 2, st); }
        CP_COMMIT();
    }
    CP_WAIT0();
    __syncthreads();

    // epilogue: per-warp 16x16 staging in smem, fused bias/relu/splits
    float* ep = (float*)(smem + EPI_OFF) + wid * 256;
#pragma unroll 1
    for (int mi = 0; mi < 2; mi++) {
#pragma unroll 1
        for (int ni = 0; ni < 4; ni++) {
            wmma::store_matrix_sync(ep, fc[mi][ni], 16, wmma::mem_row_major);
            __syncwarp();
            int mb = m0 + wr * 32 + mi * 16;
            int nb = n0 + wc * 64 + ni * 16;
#pragma unroll
            for (int e = 0; e < 8; e++) {
                int idx = lane * 8 + e;
                int row = idx >> 4, col = idx & 15;
                int m = mb + row, n = nb + col;
                float v = ep[idx];
                if (MODE == 2) {
                    int pix = m & 1023, nimg = m >> 10;
                    int y = pix >> 5, x = pix & 31;
                    int cls = ((y == 0) ? 0 : (y == 31) ? 6 : 3)
                            + ((x == 0) ? 0 : (x == 31) ? 2 : 1);
                    v += g_sp[(size_t)pix * VD + n] + g_thn[((size_t)nimg * 9 + cls) * VD + n];
                    outf[(size_t)m * ldc + n] = fmaxf(v, 0.f);
                } else {
                    v += bias[n];
                    if (MODE == 1) v = fmaxf(v, 0.f);
                    size_t o = (size_t)m * ldc + n;
                    if (outf) outf[o] = v;
                    if (outh) split2(v, outh, outl, o);
                }
            }
            __syncwarp();
        }
    }
}

// ---------------- layout / prep kernels ----------------
__global__ __launch_bounds__(256) void transpose_in_k(const float* __restrict__ in) {
    int idx = blockIdx.x * 256 + threadIdx.x;
    int c = idx & 255;
    int rest = idx >> 8;
    int pimg = rest & 1023;
    int n = rest >> 10;
    float v = in[((size_t)(n * VD + c) << 10) + pimg];
    g_feat[idx] = v;
    split2(v, g_feat_h, g_feat_l, idx);
}

__global__ __launch_bounds__(256) void transpose_out_k(float* __restrict__ o) {
    int idx = blockIdx.x * 256 + threadIdx.x;
    int pimg = idx & 1023;
    int rest = idx >> 10;
    int c = rest & 255;
    int n = rest >> 8;
    o[idx] = g_feat[((((size_t)n << 10) + pimg) << 8) + c];
}

__global__ __launch_bounds__(256) void wprep_k(
    const float* __restrict__ mconv, const float* __restrict__ ipw,
    const float* __restrict__ ipb, const float* __restrict__ opw,
    const float* __restrict__ l1w, const float* __restrict__ l2w)
{
    int idx = blockIdx.x * 256 + threadIdx.x;
    if (idx < VD * KCONV) {
        int co = idx / KCONV, k = idx % KCONV;
        int tap = k >> 8, ci = k & 255;
        split2(mconv[((size_t)co * 776 + ci) * 9 + tap], g_wc_h, g_wc_l, idx);
    }
    if (idx < 2 * VD * VD) {
        int n = idx >> 8, k = idx & 255;
        split2(ipw[(size_t)(256 + n) * 256 + k], g_wkv_h, g_wkv_l, idx);
        if (k == 0) g_bkv[n] = ipb[256 + n];
    }
    if (idx < VD * VD) {
        split2(opw[idx], g_wo_h, g_wo_l, idx);
        split2(l1w[idx], g_w1_h, g_w1_l, idx);
        split2(l2w[idx], g_w2_h, g_w2_l, idx);
    }
}

__global__ __launch_bounds__(256) void qh_k(
    const float* __restrict__ emb, const float* __restrict__ qw,
    const float* __restrict__ qb, const float* __restrict__ ipw,
    const float* __restrict__ ipb)
{
    int row = blockIdx.x;
    int s = row / 16, n = row % 16;
    int tid = threadIdx.x;
    __shared__ float esh[EMBD];
    __shared__ float qsh[VD];
    for (int i = tid; i < EMBD; i += 256)
        esh[i] = emb[((size_t)(n * SEQL + s)) * EMBD + i];
    __syncthreads();
    float acc = qb[tid];
    for (int k = 0; k < EMBD; k++) acc += esh[k] * qw[(size_t)tid * EMBD + k];
    qsh[tid] = fmaxf(acc, 0.f);
    __syncthreads();
    float acc2 = ipb[tid];
    for (int k = 0; k < VD; k++) acc2 += qsh[k] * ipw[(size_t)tid * 256 + k];
    g_qh[(size_t)row * VD + tid] = acc2;
}

__global__ __launch_bounds__(256) void thn_k(
    const float* __restrict__ hn, const float* __restrict__ mconv)
{
    int cls = blockIdx.x;
    int co = blockIdx.y * 16 + (threadIdx.x >> 4);
    int n  = threadIdx.x & 15;
    int yt = cls / 3, xt = cls % 3;
    int ky0 = (yt == 0) ? 1 : 0, ky1 = (yt == 2) ? 1 : 2;
    int kx0 = (xt == 0) ? 1 : 0, kx1 = (xt == 2) ? 1 : 2;
    float acc = 0.f;
    for (int c = 0; c < HND; c++) {
        const float* base = mconv + ((size_t)co * 776 + 264 + c) * 9;
        float w = 0.f;
        for (int ky = ky0; ky <= ky1; ky++)
            for (int kx = kx0; kx <= kx1; kx++)
                w += base[ky * 3 + kx];
        acc += hn[(size_t)n * HND + c] * w;
    }
    g_thn[((size_t)n * 9 + cls) * VD + co] = acc;
}

__global__ __launch_bounds__(1024) void sp_k(const float* __restrict__ mconv) {
    int co = blockIdx.x;
    int p = threadIdx.x;
    int y = p >> 5, x = p & 31;
    __shared__ float w[8][9];
    if (threadIdx.x < 72) {
        int j = threadIdx.x / 9, t = threadIdx.x % 9;
        w[j][t] = mconv[((size_t)co * 776 + 256 + j) * 9 + t];
    }
    __syncthreads();
    float acc = 0.f;
    for (int ky = 0; ky < 3; ky++) {
        int yy = y + ky - 1;
        if ((unsigned)yy >= 32u) continue;
        for (int kx = 0; kx < 3; kx++) {
            int xx = x + kx - 1;
            if ((unsigned)xx >= 32u) continue;
            float xmin = xx * 0.0625f - 1.f, ymin = yy * 0.0625f - 1.f;
            float xmax = xmin + 0.0625f,     ymax = ymin + 0.0625f;
            int t = ky * 3 + kx;
            acc += xmin * w[0][t] + ymin * w[1][t] + xmax * w[2][t] + ymax * w[3][t]
                 + 0.5f * (xmin + xmax) * w[4][t] + 0.5f * (ymin + ymax) * w[5][t]
                 + 0.03125f * w[6][t] + 0.03125f * w[7][t];
        }
    }
    g_sp[(size_t)p * VD + co] = acc;
}

// ---------------- layernorm (+residual, +hi/lo emit, gated) ----------------
__global__ __launch_bounds__(256) void ln_k(
    const float* __restrict__ x, const float* __restrict__ res,
    const float* __restrict__ g, const float* __restrict__ b,
    float* __restrict__ out, bf16* __restrict__ oh, bf16* __restrict__ ol,
    const int* __restrict__ words, int s)
{
    if (words && words[s] == 0) return;
    int row = blockIdx.x, tid = threadIdx.x;
    size_t off = (size_t)row * VD + tid;
    float v = x[off];
    if (res) v += res[off];
    float sum = v, sq = v * v;
#pragma unroll
    for (int o_ = 16; o_; o_ >>= 1) {
        sum += __shfl_xor_sync(0xffffffffu, sum, o_);
        sq  += __shfl_xor_sync(0xffffffffu, sq,  o_);
    }
    __shared__ float rs[8], rq[8];
    if ((tid & 31) == 0) { rs[tid >> 5] = sum; rq[tid >> 5] = sq; }
    __syncthreads();
    float ts = 0.f, tq = 0.f;
#pragma unroll
    for (int i = 0; i < 8; i++) { ts += rs[i]; tq += rq[i]; }
    float mean = ts * (1.f / VD);
    float var = tq * (1.f / VD) - mean * mean;
    float y = (v - mean) * rsqrtf(var + 1e-5f) * g[tid] + b[tid];
    if (out) out[off] = y;
    if (oh) split2(y, oh, ol, off);
}

// ---------------- cross-batch attention ----------------
__global__ __launch_bounds__(256) void attn_k(int s) {
    int p = blockIdx.x;
    int h = blockIdx.y;
    __shared__ float Q[16][128];
    __shared__ float Kk[16][129];
    __shared__ float V[16][128];
    __shared__ float At[16][17];
    int tid = threadIdx.x;
    for (int i = tid; i < 2048; i += 256) {
        int n = i >> 7, d = i & 127;
        size_t base = ((size_t)(n * PP + p)) * (2 * VD);
        Kk[n][d] = g_khvv[base + h * 128 + d];
        V [n][d] = g_khvv[base + 256 + h * 128 + d];
        Q [n][d] = g_qh[((size_t)(s * 16 + n)) * VD + h * 128 + d];
    }
    __syncthreads();
    int l = tid >> 4, m = tid & 15;
    float acc = 0.f;
#pragma unroll 8
    for (int d = 0; d < 128; d++) acc += Q[l][d] * Kk[m][d];
    acc *= 0.08838834764831845f;
    float mx = acc;
#pragma unroll
    for (int o_ = 8; o_; o_ >>= 1) mx = fmaxf(mx, __shfl_xor_sync(0xffffffffu, mx, o_));
    float e = __expf(acc - mx);
    float sm = e;
#pragma unroll
    for (int o_ = 8; o_; o_ >>= 1) sm += __shfl_xor_sync(0xffffffffu, sm, o_);
    At[l][m] = e / sm;
    __syncthreads();
    for (int i = tid; i < 2048; i += 256) {
        int l2 = i >> 7, d = i & 127;
        float a = 0.f;
#pragma unroll
        for (int mm = 0; mm < 16; mm++) a += At[l2][mm] * V[mm][d];
        split2(a, g_o_h, g_o_l, ((size_t)(l2 * PP + p)) * VD + h * 128 + d);
    }
}

// ---------------- host orchestration ----------------
extern "C" void kernel_launch(void* const* d_in, const int* in_sizes, int n_in,
                              void* d_out, int out_size)
{
    const float* hn        = (const float*)d_in[1];
    const float* feature   = (const float*)d_in[2];
    const float* embedding = (const float*)d_in[3];
    const int*   words     = (const int*)  d_in[4];
    const float* qconv_w   = (const float*)d_in[5];
    const float* qconv_b   = (const float*)d_in[6];
    const float* mconv_w   = (const float*)d_in[7];
    const float* mnorm_g   = (const float*)d_in[8];
    const float* mnorm_b   = (const float*)d_in[9];
    const float* in_proj_w = (const float*)d_in[10];
    const float* in_proj_b = (const float*)d_in[11];
    const float* out_proj_w= (const float*)d_in[12];
    const float* out_proj_b= (const float*)d_in[13];
    const float* norm_g    = (const float*)d_in[14];
    const float* norm_b    = (const float*)d_in[15];
    const float* lin1_w    = (const float*)d_in[16];
    const float* lin1_b    = (const float*)d_in[17];
    const float* lin2_w    = (const float*)d_in[18];
    const float* lin2_b    = (const float*)d_in[19];
    const float* normf_g   = (const float*)d_in[20];
    const float* normf_b   = (const float*)d_in[21];
    float* out = (float*)d_out;

    float *p_tpre, *p_t, *p_khvv, *p_fea, *p_tmp, *p_tmp2, *p_feat, *p_bkv;
    bf16 *p_feat_h, *p_feat_l, *p_t_h, *p_t_l, *p_o_h, *p_o_l, *p_fea_h, *p_fea_l, *p_l1_h, *p_l1_l;
    bf16 *p_wc_h, *p_wc_l, *p_wkv_h, *p_wkv_l, *p_wo_h, *p_wo_l, *p_w1_h, *p_w1_l, *p_w2_h, *p_w2_l;
    cudaGetSymbolAddress((void**)&p_feat,  g_feat);
    cudaGetSymbolAddress((void**)&p_tpre,  g_tpre);
    cudaGetSymbolAddress((void**)&p_t,     g_t);
    cudaGetSymbolAddress((void**)&p_khvv,  g_khvv);
    cudaGetSymbolAddress((void**)&p_fea,   g_fea);
    cudaGetSymbolAddress((void**)&p_tmp,   g_tmp);
    cudaGetSymbolAddress((void**)&p_tmp2,  g_tmp2);
    cudaGetSymbolAddress((void**)&p_bkv,   g_bkv);
    cudaGetSymbolAddress((void**)&p_feat_h, g_feat_h);
    cudaGetSymbolAddress((void**)&p_feat_l, g_feat_l);
    cudaGetSymbolAddress((void**)&p_t_h,   g_t_h);
    cudaGetSymbolAddress((void**)&p_t_l,   g_t_l);
    cudaGetSymbolAddress((void**)&p_o_h,   g_o_h);
    cudaGetSymbolAddress((void**)&p_o_l,   g_o_l);
    cudaGetSymbolAddress((void**)&p_fea_h, g_fea_h);
    cudaGetSymbolAddress((void**)&p_fea_l, g_fea_l);
    cudaGetSymbolAddress((void**)&p_l1_h,  g_l1_h);
    cudaGetSymbolAddress((void**)&p_l1_l,  g_l1_l);
    cudaGetSymbolAddress((void**)&p_wc_h,  g_wc_h);
    cudaGetSymbolAddress((void**)&p_wc_l,  g_wc_l);
    cudaGetSymbolAddress((void**)&p_wkv_h, g_wkv_h);
    cudaGetSymbolAddress((void**)&p_wkv_l, g_wkv_l);
    cudaGetSymbolAddress((void**)&p_wo_h,  g_wo_h);
    cudaGetSymbolAddress((void**)&p_wo_l,  g_wo_l);
    cudaGetSymbolAddress((void**)&p_w1_h,  g_w1_h);
    cudaGetSymbolAddress((void**)&p_w1_l,  g_w1_l);
    cudaGetSymbolAddress((void**)&p_w2_h,  g_w2_h);
    cudaGetSymbolAddress((void**)&p_w2_l,  g_w2_l);

    cudaFuncSetAttribute(gemm_wmma<0>, cudaFuncAttributeMaxDynamicSharedMemorySize, SM_TOTAL);
    cudaFuncSetAttribute(gemm_wmma<1>, cudaFuncAttributeMaxDynamicSharedMemorySize, SM_TOTAL);
    cudaFuncSetAttribute(gemm_wmma<2>, cudaFuncAttributeMaxDynamicSharedMemorySize, SM_TOTAL);

    transpose_in_k<<<M_TOT, 256>>>(feature);
    wprep_k<<<(VD * KCONV + 255) / 256, 256>>>(mconv_w, in_proj_w, in_proj_b,
                                               out_proj_w, lin1_w, lin2_w);
    qh_k<<<SEQL * NB, 256>>>(embedding, qconv_w, qconv_b, in_proj_w, in_proj_b);
    thn_k<<<dim3(9, 16), 256>>>(hn, mconv_w);
    sp_k<<<VD, 1024>>>(mconv_w);

    for (int s = 0; s < SEQL; s++) {
        // conv: D = feat (x) Wconv, +sp+thn, relu -> tpre   (K=2304, C=3*36)
        gemm_wmma<2><<<dim3(1, 128), 512, SM_TOTAL>>>(p_feat_h, p_feat_l, p_wc_h, p_wc_l,
            nullptr, p_tpre, nullptr, nullptr, KCONV, VD, 108, 36);
        // mnorm -> t (fp32 + hi/lo)
        ln_k<<<M_TOT, 256>>>(p_tpre, nullptr, mnorm_g, mnorm_b, p_t, p_t_h, p_t_l, nullptr, 0);
        // KV = t @ Wkv^T + b  (N=512)
        gemm_wmma<0><<<dim3(2, 128), 512, SM_TOTAL>>>(p_t_h, p_t_l, p_wkv_h, p_wkv_l,
            p_bkv, p_khvv, nullptr, nullptr, VD, 2 * VD, 12, 4);
        attn_k<<<dim3(PP, 2), 256>>>(s);
        // out_proj -> tmp
        gemm_wmma<0><<<dim3(1, 128), 512, SM_TOTAL>>>(p_o_h, p_o_l, p_wo_h, p_wo_l,
            out_proj_b, p_tmp, nullptr, nullptr, VD, VD, 12, 4);
        // norm(t + tmp) -> fea (fp32 + hi/lo)
        ln_k<<<M_TOT, 256>>>(p_tmp, p_t, norm_g, norm_b, p_fea, p_fea_h, p_fea_l, nullptr, 0);
        // lin1 + relu -> l1 (hi/lo only)
        gemm_wmma<1><<<dim3(1, 128), 512, SM_TOTAL>>>(p_fea_h, p_fea_l, p_w1_h, p_w1_l,
            lin1_b, nullptr, p_l1_h, p_l1_l, VD, VD, 12, 4);
        // lin2 -> tmp2
        gemm_wmma<0><<<dim3(1, 128), 512, SM_TOTAL>>>(p_l1_h, p_l1_l, p_w2_h, p_w2_l,
            lin2_b, p_tmp2, nullptr, nullptr, VD, VD, 12, 4);
        // normf(fea + tmp2) -> feat (fp32 + hi/lo), gated by words[s]
        ln_k<<<M_TOT, 256>>>(p_tmp2, p_fea, normf_g, normf_b, p_feat, p_feat_h, p_feat_l, words, s);
    }

    transpose_out_k<<<M_TOT, 256>>>(out);
}

// round 13
// speedup vs baseline: 1.8780x; 1.8780x over previous
#include <cuda_runtime.h>
#include <cuda_fp16.h>
#include <mma.h>
#include <cstdint>

#define NB 16
#define SEQL 20
#define PP 1024
#define VD 256
#define HND 512
#define EMBD 300
#define M_TOT (NB*PP)      // 16384
#define KCONV 2304

typedef __half h16;
using namespace nvcuda;

// ---------------- device scratch ----------------
__device__ float g_feat [M_TOT*VD];
__device__ float g_tpre [M_TOT*VD];
__device__ float g_t    [M_TOT*VD];
__device__ float g_khvv [M_TOT*2*VD];
__device__ float g_fea  [M_TOT*VD];
__device__ float g_tmp  [M_TOT*VD];
__device__ float g_tmp2 [M_TOT*VD];
__device__ float g_qh   [SEQL*NB*VD];
__device__ float g_thn  [NB*9*VD];
__device__ float g_sp   [PP*VD];
__device__ float g_bkv  [2*VD];

// fp16 activation buffers (single-rounded, no lo)
__device__ h16 g_feat_h[M_TOT*VD];
__device__ h16 g_t_h   [M_TOT*VD];
__device__ h16 g_o_h   [M_TOT*VD];
__device__ h16 g_fea_h [M_TOT*VD];
__device__ h16 g_l1_h  [M_TOT*VD];

// fp16 hi/lo weights, [n][k] layout (2-term compensated split)
__device__ h16 g_wc_h[VD*KCONV], g_wc_l[VD*KCONV];
__device__ h16 g_wkv_h[2*VD*VD], g_wkv_l[2*VD*VD];
__device__ h16 g_wo_h[VD*VD],    g_wo_l[VD*VD];
__device__ h16 g_w1_h[VD*VD],    g_w1_l[VD*VD];
__device__ h16 g_w2_h[VD*VD],    g_w2_l[VD*VD];

// ---------------- helpers (base-target only) ----------------
__device__ __forceinline__ uint32_t smem_u32(const void* p) {
    uint32_t a;
    asm("{ .reg .u64 t; cvta.to.shared.u64 t, %1; cvt.u32.u64 %0, t; }" : "=r"(a) : "l"(p));
    return a;
}
#define CP_COMMIT()      asm volatile("cp.async.commit_group;" ::: "memory")
#define CP_WAIT1()       asm volatile("cp.async.wait_group 1;" ::: "memory")
#define CP_WAIT0()       asm volatile("cp.async.wait_group 0;" ::: "memory")
#define CPA16(d, s)      asm volatile("cp.async.ca.shared.global [%0], [%1], 16;" :: "r"(d), "l"(s) : "memory")
#define CPA16Z(d, s, sz) asm volatile("cp.async.ca.shared.global [%0], [%1], 16, %2;" :: "r"(d), "l"(s), "r"(sz) : "memory")

__device__ __forceinline__ void wsplit(float v, h16* h, h16* l, size_t i) {
    h16 hh = __float2half(v);
    h[i] = hh;
    l[i] = __float2half(v - __half2float(hh));
}

// ---------------- smem layout for gemm_wmma (R6-proven config) ----------------
// K-chunk 32, rows of 40 fp16 (80 B)
// per stage: A 128x40x2 = 10240 B | B 128x40x2 = 10240 B
#define LDS 40
#define ST_STRIDE 20480
#define B_OFF 10240
#define EPI_OFF 40960
#define SM_TOTAL (40960 + 8192)

// ---------------- wmma GEMM: C[128 x 128] per CTA, 256 threads ----------------
// 2-term split: seg0 Ah*Bh, seg1 Ah*Bl  (weight rounding fully compensated)
// MODE 0: out = D + bias (fp32 and/or fp16)
// MODE 1: out = relu(D + bias) -> fp16 only
// MODE 2 (conv): out = relu(D + sp + thn) -> fp32; A gathered with 3x3 halo
template<int MODE> __global__ void __launch_bounds__(256)
gemm_wmma(const h16* __restrict__ Ah,
          const h16* __restrict__ Bh, const h16* __restrict__ Bl,
          const float* __restrict__ bias,
          float* __restrict__ outf, h16* __restrict__ outh,
          int K, int ldc, int C, int cps)
{
    extern __shared__ char smem[];
    uint32_t sb = smem_u32(smem);
    int tid = threadIdx.x, wid = tid >> 5, lane = tid & 31;
    int wr = wid >> 1, wc = wid & 1;          // warp grid 4x2: 32-row x 64-col tiles
    int m0 = blockIdx.y * 128, n0 = blockIdx.x * 128;

    auto loadA = [&](int c, int st) {
        int seg = c / cps;
        int kk = (c - seg * cps) * 32;
        uint32_t ab = sb + st * ST_STRIDE;
        if (MODE == 2) {
            int tap = kk >> 8, ci0 = kk & 255;
            int dy = tap / 3 - 1, dx = tap % 3 - 1;
            int nimg = m0 >> 10;
#pragma unroll
            for (int r = 0; r < 2; r++) {
                int e = tid + r * 256;
                int row = e >> 2, kq = (e & 3) * 8;
                int pix = (m0 + row) & 1023;
                int yy = (pix >> 5) + dy, xx = (pix & 31) + dx;
                bool ok = ((unsigned)yy < 32u) && ((unsigned)xx < 32u);
                const h16* s = ok ? (Ah + (((size_t)((nimg << 10) + (yy << 5) + xx)) << 8) + ci0 + kq) : Ah;
                CPA16Z(ab + (row * LDS + kq) * 2, s, ok ? 16u : 0u);
            }
        } else {
#pragma unroll
            for (int r = 0; r < 2; r++) {
                int e = tid + r * 256;
                int row = e >> 2, kq = (e & 3) * 8;
                const h16* s = Ah + (size_t)(m0 + row) * K + kk + kq;
                CPA16(ab + (row * LDS + kq) * 2, s);
            }
        }
    };
    auto loadB = [&](int c, int st) {
        int seg = c / cps;
        int kk = (c - seg * cps) * 32;
        const h16* src = (seg == 1) ? Bl : Bh;
        uint32_t bb = sb + st * ST_STRIDE + B_OFF;
#pragma unroll
        for (int r = 0; r < 2; r++) {
            int e = tid + r * 256;
            int row = e >> 2, kq = (e & 3) * 8;
            const h16* s = src + (size_t)(n0 + row) * K + kk + kq;
            CPA16(bb + (row * LDS + kq) * 2, s);
        }
    };

    wmma::fragment<wmma::accumulator, 16, 16, 16, float> fc[2][4];
#pragma unroll
    for (int mi = 0; mi < 2; mi++)
#pragma unroll
        for (int ni = 0; ni < 4; ni++) wmma::fill_fragment(fc[mi][ni], 0.f);

    loadA(0, 0); loadB(0, 0); CP_COMMIT();
    if (C > 1) { loadA(1, 1); loadB(1, 1); }
    CP_COMMIT();

    for (int c = 0; c < C; c++) {
        int st = c & 1;
        CP_WAIT1();
        __syncthreads();
        const h16* As = (const h16*)(smem + st * ST_STRIDE);
        const h16* Bs = (const h16*)(smem + st * ST_STRIDE + B_OFF);
#pragma unroll
        for (int ks = 0; ks < 32; ks += 16) {
            wmma::fragment<wmma::matrix_a, 16, 16, 16, h16, wmma::row_major> fa[2];
            wmma::fragment<wmma::matrix_b, 16, 16, 16, h16, wmma::col_major> fb[4];
#pragma unroll
            for (int mi = 0; mi < 2; mi++)
                wmma::load_matrix_sync(fa[mi], As + (wr * 32 + mi * 16) * LDS + ks, LDS);
#pragma unroll
            for (int ni = 0; ni < 4; ni++)
                wmma::load_matrix_sync(fb[ni], Bs + (wc * 64 + ni * 16) * LDS + ks, LDS);
#pragma unroll
            for (int mi = 0; mi < 2; mi++)
#pragma unroll
                for (int ni = 0; ni < 4; ni++)
                    wmma::mma_sync(fc[mi][ni], fa[mi], fb[ni], fc[mi][ni]);
        }
        __syncthreads();
        if (c + 2 < C) { loadA(c + 2, st); loadB(c + 2, st); }
        CP_COMMIT();
    }
    CP_WAIT0();
    __syncthreads();

    // epilogue: per-warp 16x16 staging in smem, fused bias/relu/convert
    float* ep = (float*)(smem + EPI_OFF) + wid * 256;
#pragma unroll 1
    for (int mi = 0; mi < 2; mi++) {
#pragma unroll 1
        for (int ni = 0; ni < 4; ni++) {
            wmma::store_matrix_sync(ep, fc[mi][ni], 16, wmma::mem_row_major);
            __syncwarp();
            int mb = m0 + wr * 32 + mi * 16;
            int nb = n0 + wc * 64 + ni * 16;
#pragma unroll
            for (int e = 0; e < 8; e++) {
                int idx = lane * 8 + e;
                int row = idx >> 4, col = idx & 15;
                int m = mb + row, n = nb + col;
                float v = ep[idx];
                if (MODE == 2) {
                    int pix = m & 1023, nimg = m >> 10;
                    int y = pix >> 5, x = pix & 31;
                    int cls = ((y == 0) ? 0 : (y == 31) ? 6 : 3)
                            + ((x == 0) ? 0 : (x == 31) ? 2 : 1);
                    v += g_sp[(size_t)pix * VD + n] + g_thn[((size_t)nimg * 9 + cls) * VD + n];
                    outf[(size_t)m * ldc + n] = fmaxf(v, 0.f);
                } else {
                    v += bias[n];
                    if (MODE == 1) v = fmaxf(v, 0.f);
                    size_t o = (size_t)m * ldc + n;
                    if (outf) outf[o] = v;
                    if (outh) outh[o] = __float2half(v);
                }
            }
            __syncwarp();
        }
    }
}

// ---------------- layout / prep kernels ----------------
__global__ __launch_bounds__(256) void transpose_in_k(const float* __restrict__ in) {
    int idx = blockIdx.x * 256 + threadIdx.x;
    int c = idx & 255;
    int rest = idx >> 8;
    int pimg = rest & 1023;
    int n = rest >> 10;
    float v = in[((size_t)(n * VD + c) << 10) + pimg];
    g_feat[idx] = v;
    g_feat_h[idx] = __float2half(v);
}

__global__ __launch_bounds__(256) void transpose_out_k(float* __restrict__ o) {
    int idx = blockIdx.x * 256 + threadIdx.x;
    int pimg = idx & 1023;
    int rest = idx >> 10;
    int c = rest & 255;
    int n = rest >> 8;
    o[idx] = g_feat[((((size_t)n << 10) + pimg) << 8) + c];
}

__global__ __launch_bounds__(256) void wprep_k(
    const float* __restrict__ mconv, const float* __restrict__ ipw,
    const float* __restrict__ ipb, const float* __restrict__ opw,
    const float* __restrict__ l1w, const float* __restrict__ l2w)
{
    int idx = blockIdx.x * 256 + threadIdx.x;
    if (idx < VD * KCONV) {
        int co = idx / KCONV, k = idx % KCONV;
        int tap = k >> 8, ci = k & 255;
        wsplit(mconv[((size_t)co * 776 + ci) * 9 + tap], g_wc_h, g_wc_l, idx);
    }
    if (idx < 2 * VD * VD) {
        int n = idx >> 8, k = idx & 255;
        wsplit(ipw[(size_t)(256 + n) * 256 + k], g_wkv_h, g_wkv_l, idx);
        if (k == 0) g_bkv[n] = ipb[256 + n];
    }
    if (idx < VD * VD) {
        wsplit(opw[idx], g_wo_h, g_wo_l, idx);
        wsplit(l1w[idx], g_w1_h, g_w1_l, idx);
        wsplit(l2w[idx], g_w2_h, g_w2_l, idx);
    }
}

__global__ __launch_bounds__(256) void qh_k(
    const float* __restrict__ emb, const float* __restrict__ qw,
    const float* __restrict__ qb, const float* __restrict__ ipw,
    const float* __restrict__ ipb)
{
    int row = blockIdx.x;
    int s = row / 16, n = row % 16;
    int tid = threadIdx.x;
    __shared__ float esh[EMBD];
    __shared__ float qsh[VD];
    for (int i = tid; i < EMBD; i += 256)
        esh[i] = emb[((size_t)(n * SEQL + s)) * EMBD + i];
    __syncthreads();
    float acc = qb[tid];
    for (int k = 0; k < EMBD; k++) acc += esh[k] * qw[(size_t)tid * EMBD + k];
    qsh[tid] = fmaxf(acc, 0.f);
    __syncthreads();
    float acc2 = ipb[tid];
    for (int k = 0; k < VD; k++) acc2 += qsh[k] * ipw[(size_t)tid * 256 + k];
    g_qh[(size_t)row * VD + tid] = acc2;
}

__global__ __launch_bounds__(256) void thn_k(
    const float* __restrict__ hn, const float* __restrict__ mconv)
{
    int cls = blockIdx.x;
    int co = blockIdx.y * 16 + (threadIdx.x >> 4);
    int n  = threadIdx.x & 15;
    int yt = cls / 3, xt = cls % 3;
    int ky0 = (yt == 0) ? 1 : 0, ky1 = (yt == 2) ? 1 : 2;
    int kx0 = (xt == 0) ? 1 : 0, kx1 = (xt == 2) ? 1 : 2;
    float acc = 0.f;
    for (int c = 0; c < HND; c++) {
        const float* base = mconv + ((size_t)co * 776 + 264 + c) * 9;
        float w = 0.f;
        for (int ky = ky0; ky <= ky1; ky++)
            for (int kx = kx0; kx <= kx1; kx++)
                w += base[ky * 3 + kx];
        acc += hn[(size_t)n * HND + c] * w;
    }
    g_thn[((size_t)n * 9 + cls) * VD + co] = acc;
}

__global__ __launch_bounds__(1024) void sp_k(const float* __restrict__ mconv) {
    int co = blockIdx.x;
    int p = threadIdx.x;
    int y = p >> 5, x = p & 31;
    __shared__ float w[8][9];
    if (threadIdx.x < 72) {
        int j = threadIdx.x / 9, t = threadIdx.x % 9;
        w[j][t] = mconv[((size_t)co * 776 + 256 + j) * 9 + t];
    }
    __syncthreads();
    float acc = 0.f;
    for (int ky = 0; ky < 3; ky++) {
        int yy = y + ky - 1;
        if ((unsigned)yy >= 32u) continue;
        for (int kx = 0; kx < 3; kx++) {
            int xx = x + kx - 1;
            if ((unsigned)xx >= 32u) continue;
            float xmin = xx * 0.0625f - 1.f, ymin = yy * 0.0625f - 1.f;
            float xmax = xmin + 0.0625f,     ymax = ymin + 0.0625f;
            int t = ky * 3 + kx;
            acc += xmin * w[0][t] + ymin * w[1][t] + xmax * w[2][t] + ymax * w[3][t]
                 + 0.5f * (xmin + xmax) * w[4][t] + 0.5f * (ymin + ymax) * w[5][t]
                 + 0.03125f * w[6][t] + 0.03125f * w[7][t];
        }
    }
    g_sp[(size_t)p * VD + co] = acc;
}

// ---------------- layernorm (+residual, +fp16 emit, gated) ----------------
__global__ __launch_bounds__(256) void ln_k(
    const float* __restrict__ x, const float* __restrict__ res,
    const float* __restrict__ g, const float* __restrict__ b,
    float* __restrict__ out, h16* __restrict__ oh,
    const int* __restrict__ words, int s)
{
    if (words && words[s] == 0) return;
    int row = blockIdx.x, tid = threadIdx.x;
    size_t off = (size_t)row * VD + tid;
    float v = x[off];
    if (res) v += res[off];
    float sum = v, sq = v * v;
#pragma unroll
    for (int o_ = 16; o_; o_ >>= 1) {
        sum += __shfl_xor_sync(0xffffffffu, sum, o_);
        sq  += __shfl_xor_sync(0xffffffffu, sq,  o_);
    }
    __shared__ float rs[8], rq[8];
    if ((tid & 31) == 0) { rs[tid >> 5] = sum; rq[tid >> 5] = sq; }
    __syncthreads();
    float ts = 0.f, tq = 0.f;
#pragma unroll
    for (int i = 0; i < 8; i++) { ts += rs[i]; tq += rq[i]; }
    float mean = ts * (1.f / VD);
    float var = tq * (1.f / VD) - mean * mean;
    float y = (v - mean) * rsqrtf(var + 1e-5f) * g[tid] + b[tid];
    if (out) out[off] = y;
    if (oh) oh[off] = __float2half(y);
}

// ---------------- cross-batch attention ----------------
__global__ __launch_bounds__(256) void attn_k(int s) {
    int p = blockIdx.x;
    int h = blockIdx.y;
    __shared__ float Q[16][128];
    __shared__ float Kk[16][129];
    __shared__ float V[16][128];
    __shared__ float At[16][17];
    int tid = threadIdx.x;
    for (int i = tid; i < 2048; i += 256) {
        int n = i >> 7, d = i & 127;
        size_t base = ((size_t)(n * PP + p)) * (2 * VD);
        Kk[n][d] = g_khvv[base + h * 128 + d];
        V [n][d] = g_khvv[base + 256 + h * 128 + d];
        Q [n][d] = g_qh[((size_t)(s * 16 + n)) * VD + h * 128 + d];
    }
    __syncthreads();
    int l = tid >> 4, m = tid & 15;
    float acc = 0.f;
#pragma unroll 8
    for (int d = 0; d < 128; d++) acc += Q[l][d] * Kk[m][d];
    acc *= 0.08838834764831845f;
    float mx = acc;
#pragma unroll
    for (int o_ = 8; o_; o_ >>= 1) mx = fmaxf(mx, __shfl_xor_sync(0xffffffffu, mx, o_));
    float e = __expf(acc - mx);
    float sm = e;
#pragma unroll
    for (int o_ = 8; o_; o_ >>= 1) sm += __shfl_xor_sync(0xffffffffu, sm, o_);
    At[l][m] = e / sm;
    __syncthreads();
    for (int i = tid; i < 2048; i += 256) {
        int l2 = i >> 7, d = i & 127;
        float a = 0.f;
#pragma unroll
        for (int mm = 0; mm < 16; mm++) a += At[l2][mm] * V[mm][d];
        g_o_h[((size_t)(l2 * PP + p)) * VD + h * 128 + d] = __float2half(a);
    }
}

// ---------------- host orchestration ----------------
extern "C" void kernel_launch(void* const* d_in, const int* in_sizes, int n_in,
                              void* d_out, int out_size)
{
    const float* hn        = (const float*)d_in[1];
    const float* feature   = (const float*)d_in[2];
    const float* embedding = (const float*)d_in[3];
    const int*   words     = (const int*)  d_in[4];
    const float* qconv_w   = (const float*)d_in[5];
    const float* qconv_b   = (const float*)d_in[6];
    const float* mconv_w   = (const float*)d_in[7];
    const float* mnorm_g   = (const float*)d_in[8];
    const float* mnorm_b   = (const float*)d_in[9];
    const float* in_proj_w = (const float*)d_in[10];
    const float* in_proj_b = (const float*)d_in[11];
    const float* out_proj_w= (const float*)d_in[12];
    const float* out_proj_b= (const float*)d_in[13];
    const float* norm_g    = (const float*)d_in[14];
    const float* norm_b    = (const float*)d_in[15];
    const float* lin1_w    = (const float*)d_in[16];
    const float* lin1_b    = (const float*)d_in[17];
    const float* lin2_w    = (const float*)d_in[18];
    const float* lin2_b    = (const float*)d_in[19];
    const float* normf_g   = (const float*)d_in[20];
    const float* normf_b   = (const float*)d_in[21];
    float* out = (float*)d_out;

    float *p_tpre, *p_t, *p_khvv, *p_fea, *p_tmp, *p_tmp2, *p_feat, *p_bkv;
    h16 *p_feat_h, *p_t_h, *p_o_h, *p_fea_h, *p_l1_h;
    h16 *p_wc_h, *p_wc_l, *p_wkv_h, *p_wkv_l, *p_wo_h, *p_wo_l, *p_w1_h, *p_w1_l, *p_w2_h, *p_w2_l;
    cudaGetSymbolAddress((void**)&p_feat,  g_feat);
    cudaGetSymbolAddress((void**)&p_tpre,  g_tpre);
    cudaGetSymbolAddress((void**)&p_t,     g_t);
    cudaGetSymbolAddress((void**)&p_khvv,  g_khvv);
    cudaGetSymbolAddress((void**)&p_fea,   g_fea);
    cudaGetSymbolAddress((void**)&p_tmp,   g_tmp);
    cudaGetSymbolAddress((void**)&p_tmp2,  g_tmp2);
    cudaGetSymbolAddress((void**)&p_bkv,   g_bkv);
    cudaGetSymbolAddress((void**)&p_feat_h, g_feat_h);
    cudaGetSymbolAddress((void**)&p_t_h,   g_t_h);
    cudaGetSymbolAddress((void**)&p_o_h,   g_o_h);
    cudaGetSymbolAddress((void**)&p_fea_h, g_fea_h);
    cudaGetSymbolAddress((void**)&p_l1_h,  g_l1_h);
    cudaGetSymbolAddress((void**)&p_wc_h,  g_wc_h);
    cudaGetSymbolAddress((void**)&p_wc_l,  g_wc_l);
    cudaGetSymbolAddress((void**)&p_wkv_h, g_wkv_h);
    cudaGetSymbolAddress((void**)&p_wkv_l, g_wkv_l);
    cudaGetSymbolAddress((void**)&p_wo_h,  g_wo_h);
    cudaGetSymbolAddress((void**)&p_wo_l,  g_wo_l);
    cudaGetSymbolAddress((void**)&p_w1_h,  g_w1_h);
    cudaGetSymbolAddress((void**)&p_w1_l,  g_w1_l);
    cudaGetSymbolAddress((void**)&p_w2_h,  g_w2_h);
    cudaGetSymbolAddress((void**)&p_w2_l,  g_w2_l);

    cudaFuncSetAttribute(gemm_wmma<0>, cudaFuncAttributeMaxDynamicSharedMemorySize, SM_TOTAL);
    cudaFuncSetAttribute(gemm_wmma<1>, cudaFuncAttributeMaxDynamicSharedMemorySize, SM_TOTAL);
    cudaFuncSetAttribute(gemm_wmma<2>, cudaFuncAttributeMaxDynamicSharedMemorySize, SM_TOTAL);

    transpose_in_k<<<M_TOT, 256>>>(feature);
    wprep_k<<<(VD * KCONV + 255) / 256, 256>>>(mconv_w, in_proj_w, in_proj_b,
                                               out_proj_w, lin1_w, lin2_w);
    qh_k<<<SEQL * NB, 256>>>(embedding, qconv_w, qconv_b, in_proj_w, in_proj_b);
    thn_k<<<dim3(9, 16), 256>>>(hn, mconv_w);
    sp_k<<<VD, 1024>>>(mconv_w);

    for (int s = 0; s < SEQL; s++) {
        // conv: D = feat (x) Wconv, +sp+thn, relu -> tpre  (2 segs x 72 chunks)
        gemm_wmma<2><<<dim3(2, 128), 256, SM_TOTAL>>>(p_feat_h, p_wc_h, p_wc_l,
            nullptr, p_tpre, nullptr, KCONV, VD, 144, 72);
        // mnorm -> t (fp32 + fp16)
        ln_k<<<M_TOT, 256>>>(p_tpre, nullptr, mnorm_g, mnorm_b, p_t, p_t_h, nullptr, 0);
        // KV = t @ Wkv^T + b  (N=512)
        gemm_wmma<0><<<dim3(4, 128), 256, SM_TOTAL>>>(p_t_h, p_wkv_h, p_wkv_l,
            p_bkv, p_khvv, nullptr, VD, 2 * VD, 16, 8);
        attn_k<<<dim3(PP, 2), 256>>>(s);
        // out_proj -> tmp
        gemm_wmma<0><<<dim3(2, 128), 256, SM_TOTAL>>>(p_o_h, p_wo_h, p_wo_l,
            out_proj_b, p_tmp, nullptr, VD, VD, 16, 8);
        // norm(t + tmp) -> fea (fp32 + fp16)
        ln_k<<<M_TOT, 256>>>(p_tmp, p_t, norm_g, norm_b, p_fea, p_fea_h, nullptr, 0);
        // lin1 + relu -> l1 (fp16 only)
        gemm_wmma<1><<<dim3(2, 128), 256, SM_TOTAL>>>(p_fea_h, p_w1_h, p_w1_l,
            lin1_b, nullptr, p_l1_h, VD, VD, 16, 8);
        // lin2 -> tmp2
        gemm_wmma<0><<<dim3(2, 128), 256, SM_TOTAL>>>(p_l1_h, p_w2_h, p_w2_l,
            lin2_b, p_tmp2, nullptr, VD, VD, 16, 8);
        // normf(fea + tmp2) -> feat (fp32 + fp16), gated by words[s]
        ln_k<<<M_TOT, 256>>>(p_tmp2, p_fea, normf_g, normf_b, p_feat, p_feat_h, words, s);
    }

    transpose_out_k<<<M_TOT, 256>>>(out);
}

// round 15
// speedup vs baseline: 2.4904x; 1.3261x over previous
#include <cuda_runtime.h>
#include <cuda_fp16.h>
#include <mma.h>
#include <cstdint>

#define NB 16
#define SEQL 20
#define PP 1024
#define VD 256
#define HND 512
#define EMBD 300
#define M_TOT (NB*PP)      // 16384
#define KCONV 2304

typedef __half h16;
using namespace nvcuda;

// ---------------- device scratch ----------------
__device__ float g_feat [M_TOT*VD];
__device__ float g_tpre [M_TOT*VD];
__device__ float g_t    [M_TOT*VD];
__device__ float g_khvv [M_TOT*2*VD];
__device__ float g_fea  [M_TOT*VD];
__device__ float g_tmp  [M_TOT*VD];
__device__ float g_tmp2 [M_TOT*VD];
__device__ float g_qh   [SEQL*NB*VD];
__device__ float g_thn  [NB*9*VD];
__device__ float g_sp   [PP*VD];
__device__ float g_bkv  [2*VD];

// fp16 activation buffers (single-rounded)
__device__ h16 g_feat_h[M_TOT*VD];
__device__ h16 g_t_h   [M_TOT*VD];
__device__ h16 g_o_h   [M_TOT*VD];
__device__ h16 g_fea_h [M_TOT*VD];
__device__ h16 g_l1_h  [M_TOT*VD];

// fp16 weights, [n][k] layout (single-rounded)
__device__ h16 g_wc_h[VD*KCONV];
__device__ h16 g_wkv_h[2*VD*VD];
__device__ h16 g_wo_h[VD*VD];
__device__ h16 g_w1_h[VD*VD];
__device__ h16 g_w2_h[VD*VD];

// ---------------- helpers (base-target only) ----------------
__device__ __forceinline__ uint32_t smem_u32(const void* p) {
    uint32_t a;
    asm("{ .reg .u64 t; cvta.to.shared.u64 t, %1; cvt.u32.u64 %0, t; }" : "=r"(a) : "l"(p));
    return a;
}
#define CP_COMMIT()      asm volatile("cp.async.commit_group;" ::: "memory")
#define CP_WAIT1()       asm volatile("cp.async.wait_group 1;" ::: "memory")
#define CP_WAIT0()       asm volatile("cp.async.wait_group 0;" ::: "memory")
#define CPA16(d, s)      asm volatile("cp.async.ca.shared.global [%0], [%1], 16;" :: "r"(d), "l"(s) : "memory")
#define CPA16Z(d, s, sz) asm volatile("cp.async.ca.shared.global [%0], [%1], 16, %2;" :: "r"(d), "l"(s), "r"(sz) : "memory")

// ---------------- smem layout for gemm_wmma (R6/R13-proven config) ----------------
// K-chunk 32, rows of 40 fp16 (80 B)
// per stage: A 128x40x2 = 10240 B | B 128x40x2 = 10240 B
#define LDS 40
#define ST_STRIDE 20480
#define B_OFF 10240
#define EPI_OFF 40960
#define SM_TOTAL (40960 + 8192)

// ---------------- wmma GEMM: C[128 x 128] per CTA, 256 threads ----------------
// Single-term fp16: C = Ah @ Bh^T  (both single-rounded)
// MODE 0: out = D + bias (fp32 and/or fp16)
// MODE 1: out = relu(D + bias) -> fp16 only
// MODE 2 (conv): out = relu(D + sp + thn) -> fp32; A gathered with 3x3 halo
template<int MODE> __global__ void __launch_bounds__(256)
gemm_wmma(const h16* __restrict__ Ah,
          const h16* __restrict__ Bh,
          const float* __restrict__ bias,
          float* __restrict__ outf, h16* __restrict__ outh,
          int K, int ldc, int C)
{
    extern __shared__ char smem[];
    uint32_t sb = smem_u32(smem);
    int tid = threadIdx.x, wid = tid >> 5, lane = tid & 31;
    int wr = wid >> 1, wc = wid & 1;          // warp grid 4x2: 32-row x 64-col tiles
    int m0 = blockIdx.y * 128, n0 = blockIdx.x * 128;

    auto loadA = [&](int c, int st) {
        int kk = c * 32;
        uint32_t ab = sb + st * ST_STRIDE;
        if (MODE == 2) {
            int tap = kk >> 8, ci0 = kk & 255;
            int dy = tap / 3 - 1, dx = tap % 3 - 1;
            int nimg = m0 >> 10;
#pragma unroll
            for (int r = 0; r < 2; r++) {
                int e = tid + r * 256;
                int row = e >> 2, kq = (e & 3) * 8;
                int pix = (m0 + row) & 1023;
                int yy = (pix >> 5) + dy, xx = (pix & 31) + dx;
                bool ok = ((unsigned)yy < 32u) && ((unsigned)xx < 32u);
                const h16* s = ok ? (Ah + (((size_t)((nimg << 10) + (yy << 5) + xx)) << 8) + ci0 + kq) : Ah;
                CPA16Z(ab + (row * LDS + kq) * 2, s, ok ? 16u : 0u);
            }
        } else {
#pragma unroll
            for (int r = 0; r < 2; r++) {
                int e = tid + r * 256;
                int row = e >> 2, kq = (e & 3) * 8;
                const h16* s = Ah + (size_t)(m0 + row) * K + kk + kq;
                CPA16(ab + (row * LDS + kq) * 2, s);
            }
        }
    };
    auto loadB = [&](int c, int st) {
        int kk = c * 32;
        uint32_t bb = sb + st * ST_STRIDE + B_OFF;
#pragma unroll
        for (int r = 0; r < 2; r++) {
            int e = tid + r * 256;
            int row = e >> 2, kq = (e & 3) * 8;
            const h16* s = Bh + (size_t)(n0 + row) * K + kk + kq;
            CPA16(bb + (row * LDS + kq) * 2, s);
        }
    };

    wmma::fragment<wmma::accumulator, 16, 16, 16, float> fc[2][4];
#pragma unroll
    for (int mi = 0; mi < 2; mi++)
#pragma unroll
        for (int ni = 0; ni < 4; ni++) wmma::fill_fragment(fc[mi][ni], 0.f);

    loadA(0, 0); loadB(0, 0); CP_COMMIT();
    if (C > 1) { loadA(1, 1); loadB(1, 1); }
    CP_COMMIT();

    for (int c = 0; c < C; c++) {
        int st = c & 1;
        CP_WAIT1();
        __syncthreads();
        const h16* As = (const h16*)(smem + st * ST_STRIDE);
        const h16* Bs = (const h16*)(smem + st * ST_STRIDE + B_OFF);
#pragma unroll
        for (int ks = 0; ks < 32; ks += 16) {
            wmma::fragment<wmma::matrix_a, 16, 16, 16, h16, wmma::row_major> fa[2];
            wmma::fragment<wmma::matrix_b, 16, 16, 16, h16, wmma::col_major> fb[4];
#pragma unroll
            for (int mi = 0; mi < 2; mi++)
                wmma::load_matrix_sync(fa[mi], As + (wr * 32 + mi * 16) * LDS + ks, LDS);
#pragma unroll
            for (int ni = 0; ni < 4; ni++)
                wmma::load_matrix_sync(fb[ni], Bs + (wc * 64 + ni * 16) * LDS + ks, LDS);
#pragma unroll
            for (int mi = 0; mi < 2; mi++)
#pragma unroll
                for (int ni = 0; ni < 4; ni++)
                    wmma::mma_sync(fc[mi][ni], fa[mi], fb[ni], fc[mi][ni]);
        }
        __syncthreads();
        if (c + 2 < C) { loadA(c + 2, st); loadB(c + 2, st); }
        CP_COMMIT();
    }
    CP_WAIT0();
    __syncthreads();

    // epilogue: per-warp 16x16 staging in smem, fused bias/relu/convert
    float* ep = (float*)(smem + EPI_OFF) + wid * 256;
#pragma unroll 1
    for (int mi = 0; mi < 2; mi++) {
#pragma unroll 1
        for (int ni = 0; ni < 4; ni++) {
            wmma::store_matrix_sync(ep, fc[mi][ni], 16, wmma::mem_row_major);
            __syncwarp();
            int mb = m0 + wr * 32 + mi * 16;
            int nb = n0 + wc * 64 + ni * 16;
#pragma unroll
            for (int e = 0; e < 8; e++) {
                int idx = lane * 8 + e;
                int row = idx >> 4, col = idx & 15;
                int m = mb + row, n = nb + col;
                float v = ep[idx];
                if (MODE == 2) {
                    int pix = m & 1023, nimg = m >> 10;
                    int y = pix >> 5, x = pix & 31;
                    int cls = ((y == 0) ? 0 : (y == 31) ? 6 : 3)
                            + ((x == 0) ? 0 : (x == 31) ? 2 : 1);
                    v += g_sp[(size_t)pix * VD + n] + g_thn[((size_t)nimg * 9 + cls) * VD + n];
                    outf[(size_t)m * ldc + n] = fmaxf(v, 0.f);
                } else {
                    v += bias[n];
                    if (MODE == 1) v = fmaxf(v, 0.f);
                    size_t o = (size_t)m * ldc + n;
                    if (outf) outf[o] = v;
                    if (outh) outh[o] = __float2half(v);
                }
            }
            __syncwarp();
        }
    }
}

// ---------------- layout / prep kernels ----------------
__global__ __launch_bounds__(256) void transpose_in_k(const float* __restrict__ in) {
    int idx = blockIdx.x * 256 + threadIdx.x;
    int c = idx & 255;
    int rest = idx >> 8;
    int pimg = rest & 1023;
    int n = rest >> 10;
    float v = in[((size_t)(n * VD + c) << 10) + pimg];
    g_feat[idx] = v;
    g_feat_h[idx] = __float2half(v);
}

__global__ __launch_bounds__(256) void transpose_out_k(float* __restrict__ o) {
    int idx = blockIdx.x * 256 + threadIdx.x;
    int pimg = idx & 1023;
    int rest = idx >> 10;
    int c = rest & 255;
    int n = rest >> 8;
    o[idx] = g_feat[((((size_t)n << 10) + pimg) << 8) + c];
}

__global__ __launch_bounds__(256) void wprep_k(
    const float* __restrict__ mconv, const float* __restrict__ ipw,
    const float* __restrict__ ipb, const float* __restrict__ opw,
    const float* __restrict__ l1w, const float* __restrict__ l2w)
{
    int idx = blockIdx.x * 256 + threadIdx.x;
    if (idx < VD * KCONV) {
        int co = idx / KCONV, k = idx % KCONV;
        int tap = k >> 8, ci = k & 255;
        g_wc_h[idx] = __float2half(mconv[((size_t)co * 776 + ci) * 9 + tap]);
    }
    if (idx < 2 * VD * VD) {
        int n = idx >> 8, k = idx & 255;
        g_wkv_h[idx] = __float2half(ipw[(size_t)(256 + n) * 256 + k]);
        if (k == 0) g_bkv[n] = ipb[256 + n];
    }
    if (idx < VD * VD) {
        g_wo_h[idx] = __float2half(opw[idx]);
        g_w1_h[idx] = __float2half(l1w[idx]);
        g_w2_h[idx] = __float2half(l2w[idx]);
    }
}

__global__ __launch_bounds__(256) void qh_k(
    const float* __restrict__ emb, const float* __restrict__ qw,
    const float* __restrict__ qb, const float* __restrict__ ipw,
    const float* __restrict__ ipb)
{
    int row = blockIdx.x;
    int s = row / 16, n = row % 16;
    int tid = threadIdx.x;
    __shared__ float esh[EMBD];
    __shared__ float qsh[VD];
    for (int i = tid; i < EMBD; i += 256)
        esh[i] = emb[((size_t)(n * SEQL + s)) * EMBD + i];
    __syncthreads();
    float acc = qb[tid];
    for (int k = 0; k < EMBD; k++) acc += esh[k] * qw[(size_t)tid * EMBD + k];
    qsh[tid] = fmaxf(acc, 0.f);
    __syncthreads();
    float acc2 = ipb[tid];
    for (int k = 0; k < VD; k++) acc2 += qsh[k] * ipw[(size_t)tid * 256 + k];
    g_qh[(size_t)row * VD + tid] = acc2;
}

__global__ __launch_bounds__(256) void thn_k(
    const float* __restrict__ hn, const float* __restrict__ mconv)
{
    int cls = blockIdx.x;
    int co = blockIdx.y * 16 + (threadIdx.x >> 4);
    int n  = threadIdx.x & 15;
    int yt = cls / 3, xt = cls % 3;
    int ky0 = (yt == 0) ? 1 : 0, ky1 = (yt == 2) ? 1 : 2;
    int kx0 = (xt == 0) ? 1 : 0, kx1 = (xt == 2) ? 1 : 2;
    float acc = 0.f;
    for (int c = 0; c < HND; c++) {
        const float* base = mconv + ((size_t)co * 776 + 264 + c) * 9;
        float w = 0.f;
        for (int ky = ky0; ky <= ky1; ky++)
            for (int kx = kx0; kx <= kx1; kx++)
                w += base[ky * 3 + kx];
        acc += hn[(size_t)n * HND + c] * w;
    }
    g_thn[((size_t)n * 9 + cls) * VD + co] = acc;
}

__global__ __launch_bounds__(1024) void sp_k(const float* __restrict__ mconv) {
    int co = blockIdx.x;
    int p = threadIdx.x;
    int y = p >> 5, x = p & 31;
    __shared__ float w[8][9];
    if (threadIdx.x < 72) {
        int j = threadIdx.x / 9, t = threadIdx.x % 9;
        w[j][t] = mconv[((size_t)co * 776 + 256 + j) * 9 + t];
    }
    __syncthreads();
    float acc = 0.f;
    for (int ky = 0; ky < 3; ky++) {
        int yy = y + ky - 1;
        if ((unsigned)yy >= 32u) continue;
        for (int kx = 0; kx < 3; kx++) {
            int xx = x + kx - 1;
            if ((unsigned)xx >= 32u) continue;
            float xmin = xx * 0.0625f - 1.f, ymin = yy * 0.0625f - 1.f;
            float xmax = xmin + 0.0625f,     ymax = ymin + 0.0625f;
            int t = ky * 3 + kx;
            acc += xmin * w[0][t] + ymin * w[1][t] + xmax * w[2][t] + ymax * w[3][t]
                 + 0.5f * (xmin + xmax) * w[4][t] + 0.5f * (ymin + ymax) * w[5][t]
                 + 0.03125f * w[6][t] + 0.03125f * w[7][t];
        }
    }
    g_sp[(size_t)p * VD + co] = acc;
}

// ---------------- layernorm (+residual, +fp16 emit, gated) ----------------
__global__ __launch_bounds__(256) void ln_k(
    const float* __restrict__ x, const float* __restrict__ res,
    const float* __restrict__ g, const float* __restrict__ b,
    float* __restrict__ out, h16* __restrict__ oh,
    const int* __restrict__ words, int s)
{
    if (words && words[s] == 0) return;
    int row = blockIdx.x, tid = threadIdx.x;
    size_t off = (size_t)row * VD + tid;
    float v = x[off];
    if (res) v += res[off];
    float sum = v, sq = v * v;
#pragma unroll
    for (int o_ = 16; o_; o_ >>= 1) {
        sum += __shfl_xor_sync(0xffffffffu, sum, o_);
        sq  += __shfl_xor_sync(0xffffffffu, sq,  o_);
    }
    __shared__ float rs[8], rq[8];
    if ((tid & 31) == 0) { rs[tid >> 5] = sum; rq[tid >> 5] = sq; }
    __syncthreads();
    float ts = 0.f, tq = 0.f;
#pragma unroll
    for (int i = 0; i < 8; i++) { ts += rs[i]; tq += rq[i]; }
    float mean = ts * (1.f / VD);
    float var = tq * (1.f / VD) - mean * mean;
    float y = (v - mean) * rsqrtf(var + 1e-5f) * g[tid] + b[tid];
    if (out) out[off] = y;
    if (oh) oh[off] = __float2half(y);
}

// ---------------- cross-batch attention ----------------
__global__ __launch_bounds__(256) void attn_k(int s) {
    int p = blockIdx.x;
    int h = blockIdx.y;
    __shared__ float Q[16][128];
    __shared__ float Kk[16][129];
    __shared__ float V[16][128];
    __shared__ float At[16][17];
    int tid = threadIdx.x;
    for (int i = tid; i < 2048; i += 256) {
        int n = i >> 7, d = i & 127;
        size_t base = ((size_t)(n * PP + p)) * (2 * VD);
        Kk[n][d] = g_khvv[base + h * 128 + d];
        V [n][d] = g_khvv[base + 256 + h * 128 + d];
        Q [n][d] = g_qh[((size_t)(s * 16 + n)) * VD + h * 128 + d];
    }
    __syncthreads();
    int l = tid >> 4, m = tid & 15;
    float acc = 0.f;
#pragma unroll 8
    for (int d = 0; d < 128; d++) acc += Q[l][d] * Kk[m][d];
    acc *= 0.08838834764831845f;
    float mx = acc;
#pragma unroll
    for (int o_ = 8; o_; o_ >>= 1) mx = fmaxf(mx, __shfl_xor_sync(0xffffffffu, mx, o_));
    float e = __expf(acc - mx);
    float sm = e;
#pragma unroll
    for (int o_ = 8; o_; o_ >>= 1) sm += __shfl_xor_sync(0xffffffffu, sm, o_);
    At[l][m] = e / sm;
    __syncthreads();
    for (int i = tid; i < 2048; i += 256) {
        int l2 = i >> 7, d = i & 127;
        float a = 0.f;
#pragma unroll
        for (int mm = 0; mm < 16; mm++) a += At[l2][mm] * V[mm][d];
        g_o_h[((size_t)(l2 * PP + p)) * VD + h * 128 + d] = __float2half(a);
    }
}

// ---------------- host orchestration ----------------
extern "C" void kernel_launch(void* const* d_in, const int* in_sizes, int n_in,
                              void* d_out, int out_size)
{
    const float* hn        = (const float*)d_in[1];
    const float* feature   = (const float*)d_in[2];
    const float* embedding = (const float*)d_in[3];
    const int*   words     = (const int*)  d_in[4];
    const float* qconv_w   = (const float*)d_in[5];
    const float* qconv_b   = (const float*)d_in[6];
    const float* mconv_w   = (const float*)d_in[7];
    const float* mnorm_g   = (const float*)d_in[8];
    const float* mnorm_b   = (const float*)d_in[9];
    const float* in_proj_w = (const float*)d_in[10];
    const float* in_proj_b = (const float*)d_in[11];
    const float* out_proj_w= (const float*)d_in[12];
    const float* out_proj_b= (const float*)d_in[13];
    const float* norm_g    = (const float*)d_in[14];
    const float* norm_b    = (const float*)d_in[15];
    const float* lin1_w    = (const float*)d_in[16];
    const float* lin1_b    = (const float*)d_in[17];
    const float* lin2_w    = (const float*)d_in[18];
    const float* lin2_b    = (const float*)d_in[19];
    const float* normf_g   = (const float*)d_in[20];
    const float* normf_b   = (const float*)d_in[21];
    float* out = (float*)d_out;

    float *p_tpre, *p_t, *p_khvv, *p_fea, *p_tmp, *p_tmp2, *p_feat, *p_bkv;
    h16 *p_feat_h, *p_t_h, *p_o_h, *p_fea_h, *p_l1_h;
    h16 *p_wc_h, *p_wkv_h, *p_wo_h, *p_w1_h, *p_w2_h;
    cudaGetSymbolAddress((void**)&p_feat,  g_feat);
    cudaGetSymbolAddress((void**)&p_tpre,  g_tpre);
    cudaGetSymbolAddress((void**)&p_t,     g_t);
    cudaGetSymbolAddress((void**)&p_khvv,  g_khvv);
    cudaGetSymbolAddress((void**)&p_fea,   g_fea);
    cudaGetSymbolAddress((void**)&p_tmp,   g_tmp);
    cudaGetSymbolAddress((void**)&p_tmp2,  g_tmp2);
    cudaGetSymbolAddress((void**)&p_bkv,   g_bkv);
    cudaGetSymbolAddress((void**)&p_feat_h, g_feat_h);
    cudaGetSymbolAddress((void**)&p_t_h,   g_t_h);
    cudaGetSymbolAddress((void**)&p_o_h,   g_o_h);
    cudaGetSymbolAddress((void**)&p_fea_h, g_fea_h);
    cudaGetSymbolAddress((void**)&p_l1_h,  g_l1_h);
    cudaGetSymbolAddress((void**)&p_wc_h,  g_wc_h);
    cudaGetSymbolAddress((void**)&p_wkv_h, g_wkv_h);
    cudaGetSymbolAddress((void**)&p_wo_h,  g_wo_h);
    cudaGetSymbolAddress((void**)&p_w1_h,  g_w1_h);
    cudaGetSymbolAddress((void**)&p_w2_h,  g_w2_h);

    cudaFuncSetAttribute(gemm_wmma<0>, cudaFuncAttributeMaxDynamicSharedMemorySize, SM_TOTAL);
    cudaFuncSetAttribute(gemm_wmma<1>, cudaFuncAttributeMaxDynamicSharedMemorySize, SM_TOTAL);
    cudaFuncSetAttribute(gemm_wmma<2>, cudaFuncAttributeMaxDynamicSharedMemorySize, SM_TOTAL);

    transpose_in_k<<<M_TOT, 256>>>(feature);
    wprep_k<<<(VD * KCONV + 255) / 256, 256>>>(mconv_w, in_proj_w, in_proj_b,
                                               out_proj_w, lin1_w, lin2_w);
    qh_k<<<SEQL * NB, 256>>>(embedding, qconv_w, qconv_b, in_proj_w, in_proj_b);
    thn_k<<<dim3(9, 16), 256>>>(hn, mconv_w);
    sp_k<<<VD, 1024>>>(mconv_w);

    for (int s = 0; s < SEQL; s++) {
        // conv: D = feat (x) Wconv, +sp+thn, relu -> tpre  (single term, 72 chunks)
        gemm_wmma<2><<<dim3(2, 128), 256, SM_TOTAL>>>(p_feat_h, p_wc_h,
            nullptr, p_tpre, nullptr, KCONV, VD, 72);
        // mnorm -> t (fp32 + fp16)
        ln_k<<<M_TOT, 256>>>(p_tpre, nullptr, mnorm_g, mnorm_b, p_t, p_t_h, nullptr, 0);
        // KV = t @ Wkv^T + b  (N=512)
        gemm_wmma<0><<<dim3(4, 128), 256, SM_TOTAL>>>(p_t_h, p_wkv_h,
            p_bkv, p_khvv, nullptr, VD, 2 * VD, 8);
        attn_k<<<dim3(PP, 2), 256>>>(s);
        // out_proj -> tmp
        gemm_wmma<0><<<dim3(2, 128), 256, SM_TOTAL>>>(p_o_h, p_wo_h,
            out_proj_b, p_tmp, nullptr, VD, VD, 8);
        // norm(t + tmp) -> fea (fp32 + fp16)
        ln_k<<<M_TOT, 256>>>(p_tmp, p_t, norm_g, norm_b, p_fea, p_fea_h, nullptr, 0);
        // lin1 + relu -> l1 (fp16 only)
        gemm_wmma<1><<<dim3(2, 128), 256, SM_TOTAL>>>(p_fea_h, p_w1_h,
            lin1_b, nullptr, p_l1_h, VD, VD, 8);
        // lin2 -> tmp2
        gemm_wmma<0><<<dim3(2, 128), 256, SM_TOTAL>>>(p_l1_h, p_w2_h,
            lin2_b, p_tmp2, nullptr, VD, VD, 8);
        // normf(fea + tmp2) -> feat (fp32 + fp16), gated by words[s]
        ln_k<<<M_TOT, 256>>>(p_tmp2, p_fea, normf_g, normf_b, p_feat, p_feat_h, words, s);
    }

    transpose_out_k<<<M_TOT, 256>>>(out);
}